// round 6
// baseline (speedup 1.0000x reference)
#include <cuda_runtime.h>

// Composite 13-tap filter: comb[k] = sum_i fd[i] * gauss[k-i]
__device__ float g_comb[16];

__global__ void build_taps_kernel(const float* __restrict__ fd,
                                  const float* __restrict__ gs) {
    int k = threadIdx.x;
    if (k < 13) {
        float s = 0.0f;
        #pragma unroll
        for (int i = 0; i < 5; ++i) {
            int j = k - i;
            if (j >= 0 && j < 9) s += fd[i] * gs[j];
        }
        g_comb[k] = s;
    }
}

static constexpr int T_IN   = 1048576;
static constexpr int T_OUT  = T_IN - 12;      // 1048564 (divisible by 4)
static constexpr int GROUPS = T_OUT / 4;      // 262141 float4 outputs per row
static constexpr int ROWS   = 8 * 4;          // B*C = 32
static constexpr int TOTAL  = ROWS * GROUPS;  // 8,388,512 threads

__global__ __launch_bounds__(256)
void fused_fir13_kernel(const float* __restrict__ x, float* __restrict__ out) {
    int gid = blockIdx.x * blockDim.x + threadIdx.x;
    if (gid >= TOTAL) return;

    int row = gid / GROUPS;
    int q   = gid - row * GROUPS;

    const float4* xin = reinterpret_cast<const float4*>(
        x + (size_t)row * T_IN) + q;

    float4 a = xin[0];
    float4 b = xin[1];
    float4 c4 = xin[2];
    float4 d = xin[3];

    float xv[16] = {a.x, a.y, a.z, a.w,
                    b.x, b.y, b.z, b.w,
                    c4.x, c4.y, c4.z, c4.w,
                    d.x, d.y, d.z, d.w};

    float c[13];
    #pragma unroll
    for (int k = 0; k < 13; ++k) c[k] = g_comb[k];

    float4 o;
    float s0 = 0.0f, s1 = 0.0f, s2 = 0.0f, s3 = 0.0f;
    #pragma unroll
    for (int k = 0; k < 13; ++k) {
        s0 = fmaf(xv[k + 0], c[k], s0);
        s1 = fmaf(xv[k + 1], c[k], s1);
        s2 = fmaf(xv[k + 2], c[k], s2);
        s3 = fmaf(xv[k + 3], c[k], s3);
    }
    o.x = s0; o.y = s1; o.z = s2; o.w = s3;

    reinterpret_cast<float4*>(out + (size_t)row * T_OUT)[q] = o;
}

extern "C" void kernel_launch(void* const* d_in, const int* in_sizes, int n_in,
                              void* d_out, int out_size) {
    const float* x  = (const float*)d_in[0];
    const float* fd = (const float*)d_in[1];
    const float* gs = (const float*)d_in[2];
    float* out = (float*)d_out;

    build_taps_kernel<<<1, 32>>>(fd, gs);

    int blocks = (TOTAL + 255) / 256;
    fused_fir13_kernel<<<blocks, 256>>>(x, out);
}

// round 8
// speedup vs baseline: 1.0056x; 1.0056x over previous
#include <cuda_runtime.h>

// Composite 13-tap filter: comb[k] = sum_i fd[i] * gauss[k-i]
__device__ float g_comb[16];

__global__ void build_taps_kernel(const float* __restrict__ fd,
                                  const float* __restrict__ gs) {
    int k = threadIdx.x;
    if (k < 13) {
        float s = 0.0f;
        #pragma unroll
        for (int i = 0; i < 5; ++i) {
            int j = k - i;
            if (j >= 0 && j < 9) s += fd[i] * gs[j];
        }
        g_comb[k] = s;
    }
}

static constexpr int T_IN   = 1048576;
static constexpr int T_OUT  = T_IN - 12;          // 1048564
static constexpr int G8     = (T_OUT + 7) / 8;    // 131071 groups of 8 (last has 4)
static constexpr int ROWS   = 8 * 4;              // B*C = 32
static constexpr int TOTAL  = ROWS * G8;          // 4,194,272 threads

__global__ __launch_bounds__(256)
void fused_fir13_k8(const float* __restrict__ x, float* __restrict__ out) {
    int gid = blockIdx.x * blockDim.x + threadIdx.x;
    if (gid >= TOTAL) return;

    int row = gid / G8;
    int q   = gid - row * G8;
    bool full = (q < G8 - 1);   // last group per row: only 4 outputs, 4 loads

    const float4* xin =
        reinterpret_cast<const float4*>(x + (size_t)row * T_IN) + q * 2;

    float4 v0 = xin[0];
    float4 v1 = xin[1];
    float4 v2 = xin[2];
    float4 v3 = xin[3];
    float4 v4 = full ? xin[4] : make_float4(0.f, 0.f, 0.f, 0.f);

    float xv[20] = {v0.x, v0.y, v0.z, v0.w,
                    v1.x, v1.y, v1.z, v1.w,
                    v2.x, v2.y, v2.z, v2.w,
                    v3.x, v3.y, v3.z, v3.w,
                    v4.x, v4.y, v4.z, v4.w};

    float c[13];
    #pragma unroll
    for (int k = 0; k < 13; ++k) c[k] = g_comb[k];

    float s0 = 0.f, s1 = 0.f, s2 = 0.f, s3 = 0.f;
    float s4 = 0.f, s5 = 0.f, s6 = 0.f, s7 = 0.f;
    #pragma unroll
    for (int k = 0; k < 13; ++k) {
        float ck = c[k];
        s0 = fmaf(xv[k + 0], ck, s0);
        s1 = fmaf(xv[k + 1], ck, s1);
        s2 = fmaf(xv[k + 2], ck, s2);
        s3 = fmaf(xv[k + 3], ck, s3);
        s4 = fmaf(xv[k + 4], ck, s4);
        s5 = fmaf(xv[k + 5], ck, s5);
        s6 = fmaf(xv[k + 6], ck, s6);
        s7 = fmaf(xv[k + 7], ck, s7);
    }

    float* orow = out + (size_t)row * T_OUT + q * 8;
    __stcs(reinterpret_cast<float4*>(orow), make_float4(s0, s1, s2, s3));
    if (full) {
        __stcs(reinterpret_cast<float4*>(orow) + 1, make_float4(s4, s5, s6, s7));
    }
}

extern "C" void kernel_launch(void* const* d_in, const int* in_sizes, int n_in,
                              void* d_out, int out_size) {
    const float* x  = (const float*)d_in[0];
    const float* fd = (const float*)d_in[1];
    const float* gs = (const float*)d_in[2];
    float* out = (float*)d_out;

    build_taps_kernel<<<1, 32>>>(fd, gs);

    int blocks = (TOTAL + 255) / 256;
    fused_fir13_k8<<<blocks, 256>>>(x, out);
}